// round 15
// baseline (speedup 1.0000x reference)
#include <cuda_runtime.h>
#include <cuda_fp16.h>
#include <cstdint>

// ============================ problem constants ============================
static constexpr int E_TOTAL = 500000;
static constexpr int MEM_D   = 100;
static constexpr int EDGE_D  = 172;
static constexpr int HID     = 128;
static constexpr int IN_D    = 472;   // 100 + 100 + 100 + 172
static constexpr int K_PAD   = 480;
static constexpr int KCHUNK  = 16;
static constexpr int NCHUNK  = K_PAD / KCHUNK;    // 30
static constexpr int TILE_M  = 256;               // edges per tile
static constexpr int NTHREADS = 512;              // 16 warps, each 16 rows x 128 cols
static constexpr int NUM_CTAS = 152;              // persistent: one per SM
static constexpr int NUM_TILES = (E_TOTAL + TILE_M - 1) / TILE_M;  // 1954

static constexpr int B_LD = 136;                  // halves; 272B row stride

// ============================ smem layout (bytes, dynamic) ============================
static constexpr int SO_B    = 0;                             // full W1: 480 x B_LD halves
static constexpr int B_BYTES = K_PAD * B_LD * 2;              // 130560
static constexpr int SO_SRC  = SO_B + B_BYTES;                // int[256]
static constexpr int SO_DST  = SO_SRC + TILE_M * 4;
static constexpr int SO_EOF  = SO_DST + TILE_M * 4;
static constexpr int SO_DT   = SO_EOF + TILE_M * 4;           // float[256]
static constexpr int SO_B1   = SO_DT  + TILE_M * 4;           // float[128]
static constexpr int SO_W2   = SO_B1  + HID * 4;              // float[128]
static constexpr int SMEM_DYN = SO_W2 + HID * 4;              // 135680 B

// fp16 w1, row-major [K_PAD x HID], zero rows 472..479.
__device__ __align__(16) __half g_w1_f16[K_PAD * HID];

__device__ __forceinline__ uint32_t smem_u32(const void* p) {
    uint32_t a;
    asm("{ .reg .u64 t; cvta.to.shared.u64 t, %1; cvt.u32.u64 %0, t; }" : "=r"(a) : "l"(p));
    return a;
}

__device__ __forceinline__ void pf_l2(const void* p) {
    asm volatile("prefetch.global.L2 [%0];" :: "l"(p));
}

// Accurate cos for |x| up to ~1e4: Cody-Waite 2-step reduction + MUFU cos.
__device__ __forceinline__ float fast_cos(float x) {
    float k = rintf(x * 0.15915494309189535f);
    float y = fmaf(-k, 6.28125f, x);
    y = fmaf(-k, 1.9353072e-3f, y);
    return __cosf(y);
}

__device__ __forceinline__ void mma16816(float d[4], const uint32_t a[4],
                                         uint32_t b0, uint32_t b1) {
    asm volatile(
        "mma.sync.aligned.m16n8k16.row.col.f32.f16.f16.f32 "
        "{%0,%1,%2,%3}, {%4,%5,%6,%7}, {%8,%9}, {%0,%1,%2,%3};"
        : "+f"(d[0]), "+f"(d[1]), "+f"(d[2]), "+f"(d[3])
        : "r"(a[0]), "r"(a[1]), "r"(a[2]), "r"(a[3]), "r"(b0), "r"(b1));
}

// ============================ prologue: w1 -> fp16 ============================
__global__ void prep_w1_kernel(const float* __restrict__ w1) {
    int idx = blockIdx.x * blockDim.x + threadIdx.x;   // 0 .. 480*128-1
    int k = idx / HID;
    float v = (k < IN_D) ? w1[idx] : 0.0f;
    g_w1_f16[idx] = __float2half(v);
}

// ============================ main kernel ============================
__global__ void __launch_bounds__(NTHREADS, 1)
tgn_growth_kernel(const int* __restrict__ src, const int* __restrict__ dst,
                  const float* __restrict__ t, const float* __restrict__ edge_attr,
                  const float* __restrict__ memory, const float* __restrict__ last_update,
                  const float* __restrict__ time_w, const float* __restrict__ time_b,
                  const float* __restrict__ b1, const float* __restrict__ w2,
                  const float* __restrict__ b2, float* __restrict__ out) {
    extern __shared__ __align__(16) char smem[];
    int*   sSrc = (int*)(smem + SO_SRC);
    int*   sDst = (int*)(smem + SO_DST);
    int*   sEof = (int*)(smem + SO_EOF);
    float* sDt  = (float*)(smem + SO_DT);
    float* sB1f = (float*)(smem + SO_B1);
    float* sW2f = (float*)(smem + SO_W2);

    const int tid = threadIdx.x;
    const int wid = tid >> 5;          // 0..15: warp owns rows [16*wid, 16*wid+16)
    const int lid = tid & 31;
    const int rl  = lid >> 2;          // 0..7
    const int c0  = (lid & 3) * 2;     // 0,2,4,6

    // ---- load full W1 into smem once (cp.async, one wait) ----
    const uint32_t bBase = smem_u32(smem + SO_B);
    for (int i = tid; i < K_PAD * 16; i += NTHREADS) {    // 480 rows x 16 16B-segs
        const int row = i >> 4, seg = i & 15;
        const __half* gsrc = g_w1_f16 + row * HID + seg * 8;
        asm volatile("cp.async.cg.shared.global [%0], [%1], 16;"
                     :: "r"(bBase + (uint32_t)(row * B_LD + seg * 8) * 2), "l"(gsrc)
                     : "memory");
    }
    asm volatile("cp.async.commit_group;" ::: "memory");
    if (tid < HID) { sB1f[tid] = b1[tid]; sW2f[tid] = w2[tid]; }
    const float bias2 = b2[0];
    asm volatile("cp.async.wait_group 0;" ::: "memory");
    __syncthreads();

    // ldmatrix.x4 lane address: lanes 0-15 -> 16 k-rows, lanes 16-31 -> +8 cols.
    const uint32_t ldmBase =
        bBase + (uint32_t)((((lid & 15) * B_LD) + ((lid >> 4) * 8)) * 2);

    // ---- persistent tile loop ----
    for (int tile = blockIdx.x; tile < NUM_TILES; tile += NUM_CTAS) {
        const int tile0 = tile * TILE_M;

        __syncthreads();   // all warps done with previous tile (offsets in regs)
        if (tid < TILE_M) {
            int e  = tile0 + tid;
            int ec = (e < E_TOTAL) ? e : (E_TOTAL - 1);
            int s  = src[ec];
            sSrc[tid] = s * MEM_D;
            sDst[tid] = dst[ec] * MEM_D;
            sDt[tid]  = t[ec] - last_update[s];
            sEof[tid] = ec * EDGE_D;
        }
        __syncthreads();

        // ---- L2-prefetch NEXT tile's gather working set (overlaps this mainloop) ----
        {
            const int ptile = tile + NUM_CTAS;
            if (ptile < NUM_TILES && tid < TILE_M) {
                int e  = ptile * TILE_M + tid;
                int ec = (e < E_TOTAL) ? e : (E_TOTAL - 1);
                const int sn = src[ec], dn = dst[ec];
                const char* ps = (const char*)(memory + sn * MEM_D);
                const char* pd = (const char*)(memory + dn * MEM_D);
                const char* pe = (const char*)(edge_attr + ec * EDGE_D);
                #pragma unroll
                for (int l = 0; l < 4; ++l) { pf_l2(ps + l * 128); pf_l2(pd + l * 128); }
                pf_l2(ps + 399); pf_l2(pd + 399);          // tail line when misaligned
                #pragma unroll
                for (int l = 0; l < 6; ++l) pf_l2(pe + l * 128);
                pf_l2(last_update + sn);
            }
        }

        // per-thread rows: wid*16 + rl and +8
        int srcO[2], dstO[2], eofO[2];
        float dtv[2];
        #pragma unroll
        for (int i = 0; i < 2; ++i) {
            const int r = wid * 16 + i * 8 + rl;
            srcO[i] = sSrc[r]; dstO[i] = sDst[r]; eofO[i] = sEof[r]; dtv[i] = sDt[r];
        }

        // 2-deep register prefetch: pre[slot][i=row][g=kgroup]
        float2 pre[2][4];
        auto gatherChunk = [&](int c, int slot) {
            const int kb = c * KCHUNK;
            #pragma unroll
            for (int i = 0; i < 2; ++i) {
                #pragma unroll
                for (int g = 0; g < 2; ++g) {
                    const int k = kb + c0 + g * 8;   // even; pairs never straddle regions
                    float2 v;
                    if (k < MEM_D) {
                        v = *reinterpret_cast<const float2*>(memory + srcO[i] + k);
                    } else if (k < 2 * MEM_D) {
                        v = *reinterpret_cast<const float2*>(memory + dstO[i] + (k - MEM_D));
                    } else if (k < 300) {
                        float2 tw2 = *reinterpret_cast<const float2*>(time_w + (k - 200));
                        float2 tb2 = *reinterpret_cast<const float2*>(time_b + (k - 200));
                        v.x = fast_cos(fmaf(dtv[i], tw2.x, tb2.x));
                        v.y = fast_cos(fmaf(dtv[i], tw2.y, tb2.y));
                    } else if (k < IN_D) {
                        v = *reinterpret_cast<const float2*>(edge_attr + eofO[i] + (k - 300));
                    } else {
                        v = make_float2(0.0f, 0.0f);
                    }
                    pre[slot][i * 2 + g] = v;
                }
            }
        };

        float acc[16][4];
        #pragma unroll
        for (int nt = 0; nt < 16; ++nt)
            #pragma unroll
            for (int q = 0; q < 4; ++q) acc[nt][q] = 0.0f;

        gatherChunk(0, 0);
        gatherChunk(1, 1);

        // ---- barrier-free mainloop (B resident; 2 chunks of LDGs in flight) ----
        #pragma unroll
        for (int c = 0; c < NCHUNK; ++c) {
            const int slot = c & 1;
            // A fragments from prefetched regs
            uint32_t aR[4];
            #pragma unroll
            for (int g = 0; g < 2; ++g)
                #pragma unroll
                for (int i = 0; i < 2; ++i) {
                    float2 v = pre[slot][i * 2 + g];
                    __half2 h2 = __floats2half2_rn(v.x, v.y);
                    aR[g * 2 + i] = *reinterpret_cast<uint32_t*>(&h2);
                }

            if (c + 2 < NCHUNK) gatherChunk(c + 2, slot);   // refill freed slot

            const uint32_t la = ldmBase + (uint32_t)(c * KCHUNK * B_LD * 2);
            #pragma unroll
            for (int ntp = 0; ntp < 8; ++ntp) {
                uint32_t b0, b1r, b2r, b3r;
                asm volatile(
                    "ldmatrix.sync.aligned.m8n8.x4.trans.shared.b16 {%0,%1,%2,%3}, [%4];"
                    : "=r"(b0), "=r"(b1r), "=r"(b2r), "=r"(b3r) : "r"(la + ntp * 32));
                mma16816(acc[2 * ntp],     aR, b0, b1r);
                mma16816(acc[2 * ntp + 1], aR, b2r, b3r);
            }
        }

        // ---- epilogue: bias + ReLU + dot(w2), fully in-warp ----
        float p1 = 0.0f, p2 = 0.0f;   // rows rl, rl+8
        #pragma unroll
        for (int nt = 0; nt < 16; ++nt) {
            const int n0 = nt * 8 + c0;
            float2 bb = *reinterpret_cast<const float2*>(&sB1f[n0]);
            float2 ww = *reinterpret_cast<const float2*>(&sW2f[n0]);
            const float* d = acc[nt];
            p1 = fmaf(fmaxf(d[0] + bb.x, 0.0f), ww.x, p1);
            p1 = fmaf(fmaxf(d[1] + bb.y, 0.0f), ww.y, p1);
            p2 = fmaf(fmaxf(d[2] + bb.x, 0.0f), ww.x, p2);
            p2 = fmaf(fmaxf(d[3] + bb.y, 0.0f), ww.y, p2);
        }
        p1 += __shfl_xor_sync(0xFFFFFFFFu, p1, 1);
        p1 += __shfl_xor_sync(0xFFFFFFFFu, p1, 2);
        p2 += __shfl_xor_sync(0xFFFFFFFFu, p2, 1);
        p2 += __shfl_xor_sync(0xFFFFFFFFu, p2, 2);
        if ((lid & 3) == 0) {
            const int e1 = tile0 + wid * 16 + rl;
            const int e2 = e1 + 8;
            if (e1 < E_TOTAL) out[e1] = p1 + bias2;
            if (e2 < E_TOTAL) out[e2] = p2 + bias2;
        }
    }
}

// ============================ launch ============================
extern "C" void kernel_launch(void* const* d_in, const int* in_sizes, int n_in,
                              void* d_out, int out_size) {
    (void)in_sizes; (void)n_in; (void)out_size;
    const int*   src         = (const int*)d_in[0];
    const int*   dst         = (const int*)d_in[1];
    const float* t           = (const float*)d_in[2];
    const float* edge_attr   = (const float*)d_in[3];
    const float* memory      = (const float*)d_in[4];
    const float* last_update = (const float*)d_in[5];
    const float* time_w      = (const float*)d_in[6];
    const float* time_b      = (const float*)d_in[7];
    const float* w1          = (const float*)d_in[8];
    const float* b1          = (const float*)d_in[9];
    const float* w2          = (const float*)d_in[10];
    const float* b2          = (const float*)d_in[11];
    float* out = (float*)d_out;

    prep_w1_kernel<<<(K_PAD * HID + 255) / 256, 256>>>(w1);

    cudaFuncSetAttribute(tgn_growth_kernel,
                         cudaFuncAttributeMaxDynamicSharedMemorySize, SMEM_DYN);
    tgn_growth_kernel<<<NUM_CTAS, NTHREADS, SMEM_DYN>>>(
        src, dst, t, edge_attr, memory, last_update, time_w, time_b, b1, w2, b2, out);
}

// round 16
// speedup vs baseline: 1.2442x; 1.2442x over previous
#include <cuda_runtime.h>
#include <cuda_fp16.h>
#include <cstdint>

// ============================ problem constants ============================
static constexpr int E_TOTAL = 500000;
static constexpr int MEM_D   = 100;
static constexpr int EDGE_D  = 172;
static constexpr int HID     = 128;
static constexpr int IN_D    = 472;   // 100 + 100 + 100 + 172
static constexpr int K_PAD   = 480;
static constexpr int KCHUNK  = 16;
static constexpr int NCHUNK  = K_PAD / KCHUNK;    // 30
static constexpr int TILE_M  = 256;               // edges per tile
static constexpr int NTHREADS = 512;              // 16 warps, each 16 rows x 128 cols
static constexpr int NUM_CTAS = 152;              // persistent: one per SM
static constexpr int NUM_TILES = (E_TOTAL + TILE_M - 1) / TILE_M;  // 1954

static constexpr int B_LD = 136;                  // halves; 272B row stride

// ============================ smem layout (bytes, dynamic) ============================
static constexpr int SO_B    = 0;                             // full W1: 480 x B_LD halves
static constexpr int B_BYTES = K_PAD * B_LD * 2;              // 130560
static constexpr int SO_SRC  = SO_B + B_BYTES;                // int[256]
static constexpr int SO_DST  = SO_SRC + TILE_M * 4;
static constexpr int SO_EOF  = SO_DST + TILE_M * 4;
static constexpr int SO_DT   = SO_EOF + TILE_M * 4;           // float[256]
static constexpr int SO_B1   = SO_DT  + TILE_M * 4;           // float[128]
static constexpr int SO_W2   = SO_B1  + HID * 4;              // float[128]
static constexpr int SMEM_DYN = SO_W2 + HID * 4;              // 135680 B

// fp16 w1, row-major [K_PAD x HID], zero rows 472..479.
__device__ __align__(16) __half g_w1_f16[K_PAD * HID];

__device__ __forceinline__ uint32_t smem_u32(const void* p) {
    uint32_t a;
    asm("{ .reg .u64 t; cvta.to.shared.u64 t, %1; cvt.u32.u64 %0, t; }" : "=r"(a) : "l"(p));
    return a;
}

// Accurate cos for |x| up to ~1e4: Cody-Waite 2-step reduction + MUFU cos.
__device__ __forceinline__ float fast_cos(float x) {
    float k = rintf(x * 0.15915494309189535f);
    float y = fmaf(-k, 6.28125f, x);
    y = fmaf(-k, 1.9353072e-3f, y);
    return __cosf(y);
}

__device__ __forceinline__ void mma16816(float d[4], const uint32_t a[4],
                                         uint32_t b0, uint32_t b1) {
    asm volatile(
        "mma.sync.aligned.m16n8k16.row.col.f32.f16.f16.f32 "
        "{%0,%1,%2,%3}, {%4,%5,%6,%7}, {%8,%9}, {%0,%1,%2,%3};"
        : "+f"(d[0]), "+f"(d[1]), "+f"(d[2]), "+f"(d[3])
        : "r"(a[0]), "r"(a[1]), "r"(a[2]), "r"(a[3]), "r"(b0), "r"(b1));
}

// ============================ prologue: w1 -> fp16 ============================
__global__ void prep_w1_kernel(const float* __restrict__ w1) {
    int idx = blockIdx.x * blockDim.x + threadIdx.x;   // 0 .. 480*128-1
    int k = idx / HID;
    float v = (k < IN_D) ? w1[idx] : 0.0f;
    g_w1_f16[idx] = __float2half(v);
}

// ============================ main kernel ============================
__global__ void __launch_bounds__(NTHREADS, 1)
tgn_growth_kernel(const int* __restrict__ src, const int* __restrict__ dst,
                  const float* __restrict__ t, const float* __restrict__ edge_attr,
                  const float* __restrict__ memory, const float* __restrict__ last_update,
                  const float* __restrict__ time_w, const float* __restrict__ time_b,
                  const float* __restrict__ b1, const float* __restrict__ w2,
                  const float* __restrict__ b2, float* __restrict__ out) {
    extern __shared__ __align__(16) char smem[];
    int*   sSrc = (int*)(smem + SO_SRC);
    int*   sDst = (int*)(smem + SO_DST);
    int*   sEof = (int*)(smem + SO_EOF);
    float* sDt  = (float*)(smem + SO_DT);
    float* sB1f = (float*)(smem + SO_B1);
    float* sW2f = (float*)(smem + SO_W2);

    const int tid = threadIdx.x;
    const int wid = tid >> 5;          // 0..15: warp owns rows [16*wid, 16*wid+16)
    const int lid = tid & 31;
    const int rl  = lid >> 2;          // 0..7
    const int c0  = (lid & 3) * 2;     // 0,2,4,6

    // ---- load full W1 into smem once (cp.async, one wait) ----
    const uint32_t bBase = smem_u32(smem + SO_B);
    for (int i = tid; i < K_PAD * 16; i += NTHREADS) {    // 480 rows x 16 16B-segs
        const int row = i >> 4, seg = i & 15;
        const __half* gsrc = g_w1_f16 + row * HID + seg * 8;
        asm volatile("cp.async.cg.shared.global [%0], [%1], 16;"
                     :: "r"(bBase + (uint32_t)(row * B_LD + seg * 8) * 2), "l"(gsrc)
                     : "memory");
    }
    asm volatile("cp.async.commit_group;" ::: "memory");
    if (tid < HID) { sB1f[tid] = b1[tid]; sW2f[tid] = w2[tid]; }
    const float bias2 = b2[0];
    asm volatile("cp.async.wait_group 0;" ::: "memory");
    __syncthreads();

    // ldmatrix.x4 lane address: lanes 0-15 -> 16 k-rows, lanes 16-31 -> +8 cols.
    const uint32_t ldmBase =
        bBase + (uint32_t)((((lid & 15) * B_LD) + ((lid >> 4) * 8)) * 2);

    // ---- persistent tile loop ----
    for (int tile = blockIdx.x; tile < NUM_TILES; tile += NUM_CTAS) {
        const int tile0 = tile * TILE_M;

        __syncthreads();   // all warps done with previous tile (offsets in regs)
        if (tid < TILE_M) {
            int e  = tile0 + tid;
            int ec = (e < E_TOTAL) ? e : (E_TOTAL - 1);
            int s  = src[ec];
            sSrc[tid] = s * MEM_D;
            sDst[tid] = dst[ec] * MEM_D;
            sDt[tid]  = t[ec] - last_update[s];
            sEof[tid] = ec * EDGE_D;
        }
        __syncthreads();

        // per-thread rows: wid*16 + rl and +8
        int srcO[2], dstO[2], eofO[2];
        float dtv[2];
        #pragma unroll
        for (int i = 0; i < 2; ++i) {
            const int r = wid * 16 + i * 8 + rl;
            srcO[i] = sSrc[r]; dstO[i] = sDst[r]; eofO[i] = sEof[r]; dtv[i] = sDt[r];
        }

        // 2-deep register prefetch: pre[slot][i=row][g=kgroup]
        float2 pre[2][4];
        auto gatherChunk = [&](int c, int slot) {
            const int kb = c * KCHUNK;
            #pragma unroll
            for (int i = 0; i < 2; ++i) {
                #pragma unroll
                for (int g = 0; g < 2; ++g) {
                    const int k = kb + c0 + g * 8;   // even; pairs never straddle regions
                    float2 v;
                    if (k < MEM_D) {
                        v = *reinterpret_cast<const float2*>(memory + srcO[i] + k);
                    } else if (k < 2 * MEM_D) {
                        v = *reinterpret_cast<const float2*>(memory + dstO[i] + (k - MEM_D));
                    } else if (k < 300) {
                        float2 tw2 = *reinterpret_cast<const float2*>(time_w + (k - 200));
                        float2 tb2 = *reinterpret_cast<const float2*>(time_b + (k - 200));
                        v.x = fast_cos(fmaf(dtv[i], tw2.x, tb2.x));
                        v.y = fast_cos(fmaf(dtv[i], tw2.y, tb2.y));
                    } else if (k < IN_D) {
                        v = *reinterpret_cast<const float2*>(edge_attr + eofO[i] + (k - 300));
                    } else {
                        v = make_float2(0.0f, 0.0f);
                    }
                    pre[slot][i * 2 + g] = v;
                }
            }
        };

        float acc[16][4];
        #pragma unroll
        for (int nt = 0; nt < 16; ++nt)
            #pragma unroll
            for (int q = 0; q < 4; ++q) acc[nt][q] = 0.0f;

        gatherChunk(0, 0);
        gatherChunk(1, 1);

        // ---- barrier-free mainloop (B resident; batched ldmatrix pipelining) ----
        #pragma unroll
        for (int c = 0; c < NCHUNK; ++c) {
            const int slot = c & 1;
            // A fragments from prefetched regs
            uint32_t aR[4];
            #pragma unroll
            for (int g = 0; g < 2; ++g)
                #pragma unroll
                for (int i = 0; i < 2; ++i) {
                    float2 v = pre[slot][i * 2 + g];
                    __half2 h2 = __floats2half2_rn(v.x, v.y);
                    aR[g * 2 + i] = *reinterpret_cast<uint32_t*>(&h2);
                }

            if (c + 2 < NCHUNK) gatherChunk(c + 2, slot);   // refill freed slot

            const uint32_t la = ldmBase + (uint32_t)(c * KCHUNK * B_LD * 2);
            // Two batches: issue 4 ldmatrix.x4 back-to-back, then their 8 MMAs.
            #pragma unroll
            for (int half = 0; half < 2; ++half) {
                uint32_t bf[4][4];
                #pragma unroll
                for (int j = 0; j < 4; ++j) {
                    const int ntp = half * 4 + j;
                    asm volatile(
                        "ldmatrix.sync.aligned.m8n8.x4.trans.shared.b16 {%0,%1,%2,%3}, [%4];"
                        : "=r"(bf[j][0]), "=r"(bf[j][1]), "=r"(bf[j][2]), "=r"(bf[j][3])
                        : "r"(la + ntp * 32));
                }
                #pragma unroll
                for (int j = 0; j < 4; ++j) {
                    const int ntp = half * 4 + j;
                    mma16816(acc[2 * ntp],     aR, bf[j][0], bf[j][1]);
                    mma16816(acc[2 * ntp + 1], aR, bf[j][2], bf[j][3]);
                }
            }
        }

        // ---- epilogue: bias + ReLU + dot(w2), fully in-warp ----
        float p1 = 0.0f, p2 = 0.0f;   // rows rl, rl+8
        #pragma unroll
        for (int nt = 0; nt < 16; ++nt) {
            const int n0 = nt * 8 + c0;
            float2 bb = *reinterpret_cast<const float2*>(&sB1f[n0]);
            float2 ww = *reinterpret_cast<const float2*>(&sW2f[n0]);
            const float* d = acc[nt];
            p1 = fmaf(fmaxf(d[0] + bb.x, 0.0f), ww.x, p1);
            p1 = fmaf(fmaxf(d[1] + bb.y, 0.0f), ww.y, p1);
            p2 = fmaf(fmaxf(d[2] + bb.x, 0.0f), ww.x, p2);
            p2 = fmaf(fmaxf(d[3] + bb.y, 0.0f), ww.y, p2);
        }
        p1 += __shfl_xor_sync(0xFFFFFFFFu, p1, 1);
        p1 += __shfl_xor_sync(0xFFFFFFFFu, p1, 2);
        p2 += __shfl_xor_sync(0xFFFFFFFFu, p2, 1);
        p2 += __shfl_xor_sync(0xFFFFFFFFu, p2, 2);
        if ((lid & 3) == 0) {
            const int e1 = tile0 + wid * 16 + rl;
            const int e2 = e1 + 8;
            if (e1 < E_TOTAL) out[e1] = p1 + bias2;
            if (e2 < E_TOTAL) out[e2] = p2 + bias2;
        }
    }
}

// ============================ launch ============================
extern "C" void kernel_launch(void* const* d_in, const int* in_sizes, int n_in,
                              void* d_out, int out_size) {
    (void)in_sizes; (void)n_in; (void)out_size;
    const int*   src         = (const int*)d_in[0];
    const int*   dst         = (const int*)d_in[1];
    const float* t           = (const float*)d_in[2];
    const float* edge_attr   = (const float*)d_in[3];
    const float* memory      = (const float*)d_in[4];
    const float* last_update = (const float*)d_in[5];
    const float* time_w      = (const float*)d_in[6];
    const float* time_b      = (const float*)d_in[7];
    const float* w1          = (const float*)d_in[8];
    const float* b1          = (const float*)d_in[9];
    const float* w2          = (const float*)d_in[10];
    const float* b2          = (const float*)d_in[11];
    float* out = (float*)d_out;

    prep_w1_kernel<<<(K_PAD * HID + 255) / 256, 256>>>(w1);

    cudaFuncSetAttribute(tgn_growth_kernel,
                         cudaFuncAttributeMaxDynamicSharedMemorySize, SMEM_DYN);
    tgn_growth_kernel<<<NUM_CTAS, NTHREADS, SMEM_DYN>>>(
        src, dst, t, edge_attr, memory, last_update, time_w, time_b, b1, w2, b2, out);
}

// round 17
// speedup vs baseline: 1.3391x; 1.0763x over previous
#include <cuda_runtime.h>
#include <cuda_fp16.h>
#include <cstdint>

// ============================ problem constants ============================
static constexpr int E_TOTAL = 500000;
static constexpr int MEM_D   = 100;
static constexpr int EDGE_D  = 172;
static constexpr int HID     = 128;
static constexpr int IN_D    = 472;   // 100 + 100 + 100 + 172
static constexpr int K_PAD   = 480;
static constexpr int KCHUNK  = 16;
static constexpr int NCHUNK  = K_PAD / KCHUNK;    // 30 (divisible by 3)
static constexpr int TILE_M  = 256;               // edges per tile
static constexpr int NTHREADS = 512;              // 16 warps, each 16 rows x 128 cols
static constexpr int NUM_CTAS = 152;              // persistent: one per SM
static constexpr int NUM_TILES = (E_TOTAL + TILE_M - 1) / TILE_M;  // 1954

static constexpr int B_LD = 136;                  // halves; 272B row stride

// ============================ smem layout (bytes, dynamic) ============================
static constexpr int SO_B    = 0;                             // full W1: 480 x B_LD halves
static constexpr int B_BYTES = K_PAD * B_LD * 2;              // 130560
static constexpr int SO_SRC  = SO_B + B_BYTES;                // int[256]
static constexpr int SO_DST  = SO_SRC + TILE_M * 4;
static constexpr int SO_EOF  = SO_DST + TILE_M * 4;
static constexpr int SO_DT   = SO_EOF + TILE_M * 4;           // float[256]
static constexpr int SO_B1   = SO_DT  + TILE_M * 4;           // float[128]
static constexpr int SO_W2   = SO_B1  + HID * 4;              // float[128]
static constexpr int SMEM_DYN = SO_W2 + HID * 4;              // 135680 B

// fp16 w1, row-major [K_PAD x HID], zero rows 472..479.
__device__ __align__(16) __half g_w1_f16[K_PAD * HID];

__device__ __forceinline__ uint32_t smem_u32(const void* p) {
    uint32_t a;
    asm("{ .reg .u64 t; cvta.to.shared.u64 t, %1; cvt.u32.u64 %0, t; }" : "=r"(a) : "l"(p));
    return a;
}

// Accurate cos for |x| up to ~1e4: Cody-Waite 2-step reduction + MUFU cos.
__device__ __forceinline__ float fast_cos(float x) {
    float k = rintf(x * 0.15915494309189535f);
    float y = fmaf(-k, 6.28125f, x);
    y = fmaf(-k, 1.9353072e-3f, y);
    return __cosf(y);
}

__device__ __forceinline__ void mma16816(float d[4], const uint32_t a[4],
                                         uint32_t b0, uint32_t b1) {
    asm volatile(
        "mma.sync.aligned.m16n8k16.row.col.f32.f16.f16.f32 "
        "{%0,%1,%2,%3}, {%4,%5,%6,%7}, {%8,%9}, {%0,%1,%2,%3};"
        : "+f"(d[0]), "+f"(d[1]), "+f"(d[2]), "+f"(d[3])
        : "r"(a[0]), "r"(a[1]), "r"(a[2]), "r"(a[3]), "r"(b0), "r"(b1));
}

__device__ __forceinline__ uint32_t pack_h2(float x, float y) {
    __half2 h2 = __floats2half2_rn(x, y);
    return *reinterpret_cast<uint32_t*>(&h2);
}

// ============================ prologue: w1 -> fp16 ============================
__global__ void prep_w1_kernel(const float* __restrict__ w1) {
    int idx = blockIdx.x * blockDim.x + threadIdx.x;   // 0 .. 480*128-1
    int k = idx / HID;
    float v = (k < IN_D) ? w1[idx] : 0.0f;
    g_w1_f16[idx] = __float2half(v);
}

// ============================ main kernel ============================
__global__ void __launch_bounds__(NTHREADS, 1)
tgn_growth_kernel(const int* __restrict__ src, const int* __restrict__ dst,
                  const float* __restrict__ t, const float* __restrict__ edge_attr,
                  const float* __restrict__ memory, const float* __restrict__ last_update,
                  const float* __restrict__ time_w, const float* __restrict__ time_b,
                  const float* __restrict__ b1, const float* __restrict__ w2,
                  const float* __restrict__ b2, float* __restrict__ out) {
    extern __shared__ __align__(16) char smem[];
    int*   sSrc = (int*)(smem + SO_SRC);
    int*   sDst = (int*)(smem + SO_DST);
    int*   sEof = (int*)(smem + SO_EOF);
    float* sDt  = (float*)(smem + SO_DT);
    float* sB1f = (float*)(smem + SO_B1);
    float* sW2f = (float*)(smem + SO_W2);

    const int tid = threadIdx.x;
    const int wid = tid >> 5;          // 0..15: warp owns rows [16*wid, 16*wid+16)
    const int lid = tid & 31;
    const int rl  = lid >> 2;          // 0..7
    const int q4  = (lid & 3) * 4;     // loader: float4 k-offset within chunk
    // shfl sources for fragment assembly (same row bits, chosen k-quarter)
    const int s0  = (lid & ~3) | ((lid & 3) >> 1);   // g=0 quarter
    const int s1  = s0 | 2;                          // g=1 quarter
    const bool subHi = (lid & 1);

    // ---- load full W1 into smem once (cp.async, one wait) ----
    const uint32_t bBase = smem_u32(smem + SO_B);
    for (int i = tid; i < K_PAD * 16; i += NTHREADS) {    // 480 rows x 16 16B-segs
        const int row = i >> 4, seg = i & 15;
        const __half* gsrc = g_w1_f16 + row * HID + seg * 8;
        asm volatile("cp.async.cg.shared.global [%0], [%1], 16;"
                     :: "r"(bBase + (uint32_t)(row * B_LD + seg * 8) * 2), "l"(gsrc)
                     : "memory");
    }
    asm volatile("cp.async.commit_group;" ::: "memory");
    if (tid < HID) { sB1f[tid] = b1[tid]; sW2f[tid] = w2[tid]; }
    const float bias2 = b2[0];
    asm volatile("cp.async.wait_group 0;" ::: "memory");
    __syncthreads();

    // ldmatrix.x4 lane address: lanes 0-15 -> 16 k-rows, lanes 16-31 -> +8 cols.
    const uint32_t ldmBase =
        bBase + (uint32_t)((((lid & 15) * B_LD) + ((lid >> 4) * 8)) * 2);

    // ---- persistent tile loop ----
    for (int tile = blockIdx.x; tile < NUM_TILES; tile += NUM_CTAS) {
        const int tile0 = tile * TILE_M;

        __syncthreads();   // all warps done with previous tile (offsets in regs)
        if (tid < TILE_M) {
            int e  = tile0 + tid;
            int ec = (e < E_TOTAL) ? e : (E_TOTAL - 1);
            int s  = src[ec];
            sSrc[tid] = s * MEM_D;
            sDst[tid] = dst[ec] * MEM_D;
            sDt[tid]  = t[ec] - last_update[s];
            sEof[tid] = ec * EDGE_D;
        }
        __syncthreads();

        // loader rows: wid*16 + i*8 + rl (i = 0,1)
        int srcO[2], dstO[2], eofO[2];
        float dtv[2];
        #pragma unroll
        for (int i = 0; i < 2; ++i) {
            const int r = wid * 16 + i * 8 + rl;
            srcO[i] = sSrc[r]; dstO[i] = sDst[r]; eofO[i] = sEof[r]; dtv[i] = sDt[r];
        }

        // 3-deep register prefetch of raw float4 row segments.
        // Lane loads X[row_i][kb+q4 .. kb+q4+3]; all region boundaries are mult-of-4
        // and all bases 16B-aligned, so float4 never straddles and is aligned.
        float4 pre[3][2];
        auto gatherChunk = [&](int c, int slot) {
            const int k4 = c * KCHUNK + q4;
            #pragma unroll
            for (int i = 0; i < 2; ++i) {
                float4 v;
                if (k4 < MEM_D) {
                    v = *reinterpret_cast<const float4*>(memory + srcO[i] + k4);
                } else if (k4 < 2 * MEM_D) {
                    v = *reinterpret_cast<const float4*>(memory + dstO[i] + (k4 - MEM_D));
                } else if (k4 < 300) {
                    float4 tw4 = *reinterpret_cast<const float4*>(time_w + (k4 - 200));
                    float4 tb4 = *reinterpret_cast<const float4*>(time_b + (k4 - 200));
                    v.x = fast_cos(fmaf(dtv[i], tw4.x, tb4.x));
                    v.y = fast_cos(fmaf(dtv[i], tw4.y, tb4.y));
                    v.z = fast_cos(fmaf(dtv[i], tw4.z, tb4.z));
                    v.w = fast_cos(fmaf(dtv[i], tw4.w, tb4.w));
                } else if (k4 < IN_D) {
                    v = *reinterpret_cast<const float4*>(edge_attr + eofO[i] + (k4 - 300));
                } else {
                    v = make_float4(0.f, 0.f, 0.f, 0.f);
                }
                pre[slot][i] = v;
            }
        };

        float acc[16][4];
        #pragma unroll
        for (int nt = 0; nt < 16; ++nt)
            #pragma unroll
            for (int q = 0; q < 4; ++q) acc[nt][q] = 0.0f;

        gatherChunk(0, 0);
        gatherChunk(1, 1);
        gatherChunk(2, 2);

        // ---- barrier-free mainloop (B resident; shfl-assembled A fragments) ----
        #pragma unroll
        for (int c = 0; c < NCHUNK; ++c) {
            const int slot = c % 3;
            // convert this lane's raw quarters to half2 (deferred conversion)
            const float4 v0 = pre[slot][0];
            const float4 v1 = pre[slot][1];
            const uint32_t a01_0 = pack_h2(v0.x, v0.y);   // i=0, k 4q..4q+1
            const uint32_t a23_0 = pack_h2(v0.z, v0.w);   // i=0, k 4q+2..4q+3
            const uint32_t a01_1 = pack_h2(v1.x, v1.y);   // i=1
            const uint32_t a23_1 = pack_h2(v1.z, v1.w);

            if (c + 3 < NCHUNK) gatherChunk(c + 3, slot);   // refill freed slot

            // assemble A fragments via shfl (source lane holds needed quarter)
            uint32_t aR[4];
            {
                const uint32_t x0a = __shfl_sync(0xFFFFFFFFu, a01_0, s0);
                const uint32_t x0b = __shfl_sync(0xFFFFFFFFu, a23_0, s0);
                const uint32_t x1a = __shfl_sync(0xFFFFFFFFu, a01_1, s0);
                const uint32_t x1b = __shfl_sync(0xFFFFFFFFu, a23_1, s0);
                const uint32_t y0a = __shfl_sync(0xFFFFFFFFu, a01_0, s1);
                const uint32_t y0b = __shfl_sync(0xFFFFFFFFu, a23_0, s1);
                const uint32_t y1a = __shfl_sync(0xFFFFFFFFu, a01_1, s1);
                const uint32_t y1b = __shfl_sync(0xFFFFFFFFu, a23_1, s1);
                aR[0] = subHi ? x0b : x0a;   // i=0, g=0
                aR[1] = subHi ? x1b : x1a;   // i=1, g=0
                aR[2] = subHi ? y0b : y0a;   // i=0, g=1
                aR[3] = subHi ? y1b : y1a;   // i=1, g=1
            }

            const uint32_t la = ldmBase + (uint32_t)(c * KCHUNK * B_LD * 2);
            #pragma unroll
            for (int ntp = 0; ntp < 8; ++ntp) {
                uint32_t b0, b1r, b2r, b3r;
                asm volatile(
                    "ldmatrix.sync.aligned.m8n8.x4.trans.shared.b16 {%0,%1,%2,%3}, [%4];"
                    : "=r"(b0), "=r"(b1r), "=r"(b2r), "=r"(b3r) : "r"(la + ntp * 32));
                mma16816(acc[2 * ntp],     aR, b0, b1r);
                mma16816(acc[2 * ntp + 1], aR, b2r, b3r);
            }
        }

        // ---- epilogue: bias + ReLU + dot(w2), fully in-warp ----
        float p1 = 0.0f, p2 = 0.0f;   // rows rl, rl+8
        const int c0 = (lid & 3) * 2;
        #pragma unroll
        for (int nt = 0; nt < 16; ++nt) {
            const int n0 = nt * 8 + c0;
            float2 bb = *reinterpret_cast<const float2*>(&sB1f[n0]);
            float2 ww = *reinterpret_cast<const float2*>(&sW2f[n0]);
            const float* d = acc[nt];
            p1 = fmaf(fmaxf(d[0] + bb.x, 0.0f), ww.x, p1);
            p1 = fmaf(fmaxf(d[1] + bb.y, 0.0f), ww.y, p1);
            p2 = fmaf(fmaxf(d[2] + bb.x, 0.0f), ww.x, p2);
            p2 = fmaf(fmaxf(d[3] + bb.y, 0.0f), ww.y, p2);
        }
        p1 += __shfl_xor_sync(0xFFFFFFFFu, p1, 1);
        p1 += __shfl_xor_sync(0xFFFFFFFFu, p1, 2);
        p2 += __shfl_xor_sync(0xFFFFFFFFu, p2, 1);
        p2 += __shfl_xor_sync(0xFFFFFFFFu, p2, 2);
        if ((lid & 3) == 0) {
            const int e1 = tile0 + wid * 16 + rl;
            const int e2 = e1 + 8;
            if (e1 < E_TOTAL) out[e1] = p1 + bias2;
            if (e2 < E_TOTAL) out[e2] = p2 + bias2;
        }
    }
}

// ============================ launch ============================
extern "C" void kernel_launch(void* const* d_in, const int* in_sizes, int n_in,
                              void* d_out, int out_size) {
    (void)in_sizes; (void)n_in; (void)out_size;
    const int*   src         = (const int*)d_in[0];
    const int*   dst         = (const int*)d_in[1];
    const float* t           = (const float*)d_in[2];
    const float* edge_attr   = (const float*)d_in[3];
    const float* memory      = (const float*)d_in[4];
    const float* last_update = (const float*)d_in[5];
    const float* time_w      = (const float*)d_in[6];
    const float* time_b      = (const float*)d_in[7];
    const float* w1          = (const float*)d_in[8];
    const float* b1          = (const float*)d_in[9];
    const float* w2          = (const float*)d_in[10];
    const float* b2          = (const float*)d_in[11];
    float* out = (float*)d_out;

    prep_w1_kernel<<<(K_PAD * HID + 255) / 256, 256>>>(w1);

    cudaFuncSetAttribute(tgn_growth_kernel,
                         cudaFuncAttributeMaxDynamicSharedMemorySize, SMEM_DYN);
    tgn_growth_kernel<<<NUM_CTAS, NTHREADS, SMEM_DYN>>>(
        src, dst, t, edge_attr, memory, last_update, time_w, time_b, b1, w2, b2, out);
}